// round 14
// baseline (speedup 1.0000x reference)
#include <cuda_runtime.h>
#include <cuda_fp16.h>
#include <cstdint>
#include <math.h>

#define BB 8
#define CC 64
#define HH 64
#define WW 64

#define BSTR 40              // words per row in fp16x2 tiles
#define SEGW 2560            // 64 rows * BSTR words  (10KB)
#define KWORDS (3*SEGW)      // packed tile: Kh | Kl | Vt (30KB)

// ---------------- scratch (static device globals; no allocation) ----------------
__device__ float g_feat[BB*CC*HH*WW];      // [B][C][H][W]
__device__ uint32_t g_wp[9*2*SEGW];        // packed conv weights per tap: [tap][Wh|Wl*2048]
__device__ uint32_t g_p1[BB*64*KWORDS];    // packed fp16 tiles per scale
__device__ uint32_t g_p2[BB*16*KWORDS];
__device__ uint32_t g_p4[BB*4*KWORDS];
__device__ float g_o1[BB*CC*4096];         // attention outputs [B][C][n]
__device__ float g_o2[BB*CC*1024];
__device__ float g_o4[BB*CC*256];

__device__ __forceinline__ uint32_t packh(float lo, float hi) {  // word = {hi16, lo16}
    uint32_t r;
    asm("cvt.rn.f16x2.f32 %0, %1, %2;" : "=r"(r) : "f"(hi), "f"(lo));
    return r;
}
__device__ __forceinline__ int islot(int u) { return 2*(u & 3) + (u >> 2); }
__device__ __forceinline__ uint32_t smem_u32(const void* p) {
    uint32_t a;
    asm("{ .reg .u64 t; cvta.to.shared.u64 t, %1; cvt.u32.u64 %0, t; }" : "=r"(a) : "l"(p));
    return a;
}
#define CP16(dst, src) asm volatile("cp.async.cg.shared.global [%0], [%1], 16;" :: "r"(dst), "l"(src))
#define CP_COMMIT()    asm volatile("cp.async.commit_group;" ::: "memory")
#define CP_WAIT1()     asm volatile("cp.async.wait_group 1;" ::: "memory")
#define CP_WAIT0()     asm volatile("cp.async.wait_group 0;" ::: "memory")
#define HEX2(x)        asm("ex2.approx.f16x2 %0, %0;" : "+r"(x))

// m16n8k16 fp16 MMA, row.col, f32 accumulate-in-place
__device__ __forceinline__ void mma16(float* d, uint32_t a0, uint32_t a1, uint32_t a2,
                                      uint32_t a3, uint32_t b0, uint32_t b1) {
    asm volatile("mma.sync.aligned.m16n8k16.row.col.f32.f16.f16.f32 "
        "{%0,%1,%2,%3}, {%4,%5,%6,%7}, {%8,%9}, {%0,%1,%2,%3};"
        : "+f"(d[0]), "+f"(d[1]), "+f"(d[2]), "+f"(d[3])
        : "r"(a0), "r"(a1), "r"(a2), "r"(a3), "r"(b0), "r"(b1));
}

// ---------------- Stage 0: weight pack (fold Laplacian, split fp16, tile layout) ----------------
__global__ void __launch_bounds__(256) wpack_kernel(const float* __restrict__ w) {
    int i = blockIdx.x*256 + threadIdx.x;          // 9*64*32 = 18432
    if (i >= 9*64*32) return;
    const float lapv[9] = {0.f, 1.f, 0.f, 1.f, -4.f, 1.f, 0.f, 1.f, 0.f};
    int tap = i >> 11;
    int rem = i & 2047;
    int oc = rem >> 5, u = rem & 31;
    int ic0 = 2*u, ic1 = 2*u + 1;
    float a = w[oc*576 + ic0*9 + tap] + ((oc == ic0) ? lapv[tap] : 0.f);
    float c = w[oc*576 + ic1*9 + tap] + ((oc == ic1) ? lapv[tap] : 0.f);
    uint32_t h = packh(a, c);
    float2 fh = __half22float2(*(const __half2*)&h);
    uint32_t l = packh((a - fh.x)*2048.f, (c - fh.y)*2048.f);
    int slot = tap*2*SEGW + oc*BSTR + (u >> 3)*8 + islot(u & 7);
    g_wp[slot]        = h;
    g_wp[slot + SEGW] = l;
}

// ---------------- Stage 1: conv as split-fp16 implicit GEMM on tensor cores ----------------
#define XROWS 108
#define XW (XROWS*BSTR)
#define CONV_SMEM ((2*XW + 3*2*SEGW) * 4)

__global__ void __launch_bounds__(128, 2) convmma_kernel(const float* __restrict__ x) {
    const int t = blockIdx.x;
    const int b = blockIdx.y;
    const int ty = t >> 2, tx = t & 3;
    extern __shared__ uint32_t cs[];
    uint32_t* Xh = cs;
    uint32_t* Xl = cs + XW;
    uint32_t* WB = cs + 2*XW;
    const int tid  = threadIdx.x;
    const int w    = tid >> 5;
    const int lane = tid & 31;
    const int g    = lane >> 2;
    const int q4   = lane & 3;
    const uint32_t sb = smem_u32(cs);

#pragma unroll
    for (int p = 0; p < 2; p++) {
#pragma unroll
        for (int j = 0; j < 10; j++) {
            int i = j*128 + tid;
            CP16(sb + (2*XW + p*2*SEGW + i*4)*4, g_wp + p*2*SEGW + i*4);
        }
        CP_COMMIT();
    }

#pragma unroll
    for (int j = 0; j < 27; j++) {
        int wi = j*128 + tid;
        int u = wi / 108, r = wi - u*108;
        int hy = r / 18, hx = r - hy*18;
        int gy = ty*4 - 1 + hy, gx = tx*16 - 1 + hx;
        float a = 0.f, c = 0.f;
        if (gy >= 0 && gy < 64 && gx >= 0 && gx < 64) {
            const float* p = x + (((size_t)b*64 + 2*u)*4096 + gy*64 + gx);
            a = p[0]; c = p[4096];
        }
        uint32_t h = packh(a, c);
        float2 fh = __half22float2(*(const __half2*)&h);
        uint32_t l = packh((a - fh.x)*2048.f, (c - fh.y)*2048.f);
        int slot = r*BSTR + (u >> 3)*8 + islot(u & 7);
        Xh[slot] = h;
        Xl[slot] = l;
    }

    float o[8][4], c[8][4];
#pragma unroll
    for (int nb = 0; nb < 8; nb++)
#pragma unroll
        for (int j = 0; j < 4; j++) { o[nb][j] = 0.f; c[nb][j] = 0.f; }

    for (int tap = 0; tap < 9; tap++) {
        if (tap == 8) CP_WAIT0(); else CP_WAIT1();
        __syncthreads();
        if (tap + 2 < 9) {
            int nb3 = (tap + 2) % 3;
#pragma unroll
            for (int j = 0; j < 10; j++) {
                int i = j*128 + tid;
                CP16(sb + (2*XW + nb3*2*SEGW + i*4)*4, g_wp + (size_t)(tap + 2)*2*SEGW + i*4);
            }
            CP_COMMIT();
        }
        const uint32_t* Wh = WB + (tap % 3)*2*SEGW;
        const uint32_t* Wl = Wh + SEGW;
        const int dy = tap / 3, dx = tap - dy*3;
        const int rA = (w + dy)*18 + g + dx;

        uint2 ahA[4], ahB[4], alA[4], alB[4];
#pragma unroll
        for (int ks = 0; ks < 4; ks++) {
            ahA[ks] = *(const uint2*)(Xh +  rA     *BSTR + ks*8 + 2*q4);
            ahB[ks] = *(const uint2*)(Xh + (rA+8)  *BSTR + ks*8 + 2*q4);
            alA[ks] = *(const uint2*)(Xl +  rA     *BSTR + ks*8 + 2*q4);
            alB[ks] = *(const uint2*)(Xl + (rA+8)  *BSTR + ks*8 + 2*q4);
        }
#pragma unroll
        for (int ks = 0; ks < 4; ks++) {
#pragma unroll
            for (int nb = 0; nb < 8; nb++) {
                uint2 bh = *(const uint2*)(Wh + (nb*8+g)*BSTR + ks*8 + 2*q4);
                uint2 bl = *(const uint2*)(Wl + (nb*8+g)*BSTR + ks*8 + 2*q4);
                mma16(o[nb], ahA[ks].x, ahB[ks].x, ahA[ks].y, ahB[ks].y, bh.x, bh.y);
                mma16(c[nb], ahA[ks].x, ahB[ks].x, ahA[ks].y, ahB[ks].y, bl.x, bl.y);
                mma16(c[nb], alA[ks].x, alB[ks].x, alA[ks].y, alB[ks].y, bh.x, bh.y);
            }
        }
    }

    const int y = ty*4 + w;
    float* fb = g_feat + (((size_t)b*64)*64 + y)*64 + tx*16;
#pragma unroll
    for (int nb = 0; nb < 8; nb++) {
        int oc = nb*8 + 2*q4;
        fb[(size_t) oc   *4096 + g    ] = fmaf(c[nb][0], 4.8828125e-4f, o[nb][0]);
        fb[(size_t)(oc+1)*4096 + g    ] = fmaf(c[nb][1], 4.8828125e-4f, o[nb][1]);
        fb[(size_t) oc   *4096 + g + 8] = fmaf(c[nb][2], 4.8828125e-4f, o[nb][2]);
        fb[(size_t)(oc+1)*4096 + g + 8] = fmaf(c[nb][3], 4.8828125e-4f, o[nb][3]);
    }
}

// ---------------- Stage 2a: fused pool + split/pack ----------------
__global__ void __launch_bounds__(256) poolpack_kernel() {
    const int t = blockIdx.x;
    const int b = blockIdx.y;
    int S, tt, N; uint32_t* gpack;
    if (t < 64)      { S = 1; tt = t;      gpack = g_p1; N = 4096; }
    else if (t < 80) { S = 2; tt = t - 64; gpack = g_p2; N = 1024; }
    else             { S = 4; tt = t - 80; gpack = g_p4; N = 256;  }
    const int WP = 64 / S;
    const float inv = 1.f / (float)(S*S);
    __shared__ float tile[64][65];
    const float* fb = g_feat + (size_t)b*CC*HH*WW;
    const int tid = threadIdx.x;

    for (int i = tid; i < 4096; i += 256) {
        int ch = i >> 6, key = i & 63;
        int n = tt*64 + key;
        int ny = n / WP, nx = n % WP;
        const float* p = fb + ch*4096 + (ny*S)*64 + nx*S;
        float s = 0.f;
        for (int dy = 0; dy < S; dy++)
            for (int dx = 0; dx < S; dx++)
                s += p[dy*64 + dx];
        tile[key][ch] = s * inv;
    }
    __syncthreads();

    uint32_t* gp = gpack + ((size_t)b*(N >> 6) + tt) * KWORDS;
#pragma unroll
    for (int j = 0; j < 8; j++) {
        int wi = j*256 + tid;
        int r = wi >> 5, u = wi & 31;
        float a = tile[r][2*u];
        float c = tile[r][2*u + 1];
        uint32_t h = packh(a, c);
        float2 fh = __half22float2(*(const __half2*)&h);
        uint32_t l = packh((a - fh.x)*2048.f, (c - fh.y)*2048.f);
        int slot = r*BSTR + (u >> 3)*8 + islot(u & 7);
        gp[slot]        = h;
        gp[SEGW + slot] = l;
    }
#pragma unroll
    for (int j = 0; j < 8; j++) {
        int wi = j*256 + tid;
        int ch = wi >> 5, lwv = wi & 31;
        float a = tile[2*lwv    ][ch];
        float c = tile[2*lwv + 1][ch];
        gp[2*SEGW + ch*BSTR + (lwv >> 3)*8 + islot(lwv & 7)] = packh(a, c);
    }
}

// ---------------- Stage 2b: flash attention, explicit 4-chunk software pipeline ----------------
// CTA: 128 q, 256 thr (8 warps). Tile = 64 keys = 4 chunks of 16. S(c+1) issued
// before softmax+PV(c) so the next chunk's MMAs cover the softmax serial chain.
#define QLW 5120
#define ATTN_SMEM ((QLW + 3*KWORDS) * 4)

// compute S for one 16-key chunk into s[2][4]
#define CHUNK_S(sdst, ch)                                                          \
    do {                                                                           \
        _Pragma("unroll")                                                          \
        for (int nb = 0; nb < 2; nb++)                                             \
            _Pragma("unroll")                                                      \
            for (int j = 0; j < 4; j++) sdst[nb][j] = 0.f;                         \
        _Pragma("unroll")                                                          \
        for (int ks = 0; ks < 4; ks++) {                                           \
            _Pragma("unroll")                                                      \
            for (int nb = 0; nb < 2; nb++) {                                       \
                uint2 bb = *(const uint2*)(Kl + (((ch)*2+nb)*8+g)*BSTR + ks*8 + 2*q4); \
                mma16(sdst[nb], qA[ks].x, qB[ks].x, qA[ks].y, qB[ks].y, bb.x, bb.y);   \
            }                                                                      \
        }                                                                          \
        _Pragma("unroll")                                                          \
        for (int ks = 0; ks < 4; ks++) {                                           \
            uint2 aA = *(const uint2*)(Ql +  r0    *BSTR + ks*8 + 2*q4);           \
            uint2 aB = *(const uint2*)(Ql + (r0+8) *BSTR + ks*8 + 2*q4);           \
            _Pragma("unroll")                                                      \
            for (int nb = 0; nb < 2; nb++) {                                       \
                uint2 bb = *(const uint2*)(Kh + (((ch)*2+nb)*8+g)*BSTR + ks*8 + 2*q4); \
                mma16(sdst[nb], aA.x, aB.x, aA.y, aB.y, bb.x, bb.y);               \
            }                                                                      \
        }                                                                          \
        _Pragma("unroll")                                                          \
        for (int nb = 0; nb < 2; nb++)                                             \
            _Pragma("unroll")                                                      \
            for (int j = 0; j < 4; j++) sdst[nb][j] *= 4.8828125e-4f;              \
        _Pragma("unroll")                                                          \
        for (int ks = 0; ks < 4; ks++) {                                           \
            _Pragma("unroll")                                                      \
            for (int nb = 0; nb < 2; nb++) {                                       \
                uint2 bb = *(const uint2*)(Kh + (((ch)*2+nb)*8+g)*BSTR + ks*8 + 2*q4); \
                mma16(sdst[nb], qA[ks].x, qB[ks].x, qA[ks].y, qB[ks].y, bb.x, bb.y);   \
            }                                                                      \
        }                                                                          \
    } while (0)

__global__ void __launch_bounds__(256, 2) attn_fused() {
    const int qtsel = blockIdx.x;
    const int b = blockIdx.y;
    int N, qt;
    const uint32_t* gpack;
    float* outp;
    if (qtsel < 32)      { N = 4096; qt = qtsel;      gpack = g_p1; outp = g_o1; }
    else if (qtsel < 40) { N = 1024; qt = qtsel - 32; gpack = g_p2; outp = g_o2; }
    else                 { N = 256;  qt = qtsel - 40; gpack = g_p4; outp = g_o4; }
    const int T = N >> 6;

    extern __shared__ uint32_t smw[];
    uint32_t* Ql = smw;
    uint32_t* KB0 = smw + QLW;

    const int tid  = threadIdx.x;
    const int w    = tid >> 5;
    const int lane = tid & 31;
    const int g    = lane >> 2;
    const int q4   = lane & 3;
    const int r0   = w*16 + g;
    const uint32_t* gb = gpack + (size_t)b*T*KWORDS;
    const uint32_t sb = smem_u32(smw);
    const uint32_t bones = (g == 0) ? 0x3C003C00u : 0u;

    // ---- preload: Qh -> KB0 (staging), Ql -> Ql region ----
#pragma unroll
    for (int j = 0; j < 10; j++) {
        int i = j*256 + tid;
        int seg = i / 640;
        int s2 = seg >> 1, p = seg & 1;
        int fo = (i - seg*640) * 4;
        const uint32_t* src = gb + (size_t)(2*qt + p)*KWORDS + s2*SEGW + fo;
        int dst = (s2 ? 0 : QLW) + p*SEGW + fo;
        CP16(sb + dst*4, src);
    }
    CP_COMMIT();
    CP_WAIT0();
    __syncthreads();

    uint2 qA[4], qB[4];
#pragma unroll
    for (int ks = 0; ks < 4; ks++) {
        qA[ks] = *(const uint2*)(KB0 +  r0    *BSTR + ks*8 + 2*q4);
        qB[ks] = *(const uint2*)(KB0 + (r0+8) *BSTR + ks*8 + 2*q4);
    }
    __syncthreads();

#pragma unroll
    for (int p = 0; p < 2; p++) {
        const uint32_t* src = gb + (size_t)p*KWORDS;
        uint32_t dstb = sb + (QLW + p*KWORDS)*4;
#pragma unroll
        for (int j = 0; j < 8; j++) {
            int i = j*256 + tid;
            if (i < 1920) CP16(dstb + i*16, src + i*4);
        }
        CP_COMMIT();
    }

    float m0 = -3.0e38f, m1 = -3.0e38f;
    float d_l[4] = {0.f, 0.f, 0.f, 0.f};
    float o[8][4];
#pragma unroll
    for (int nb = 0; nb < 8; nb++)
#pragma unroll
        for (int j = 0; j < 4; j++) o[nb][j] = 0.f;

    const float L2E = 1.4426950408889634f;
    int buf = 0;
    for (int kb = 0; kb < T; kb++) {
        if (kb == T - 1) CP_WAIT0(); else CP_WAIT1();
        __syncthreads();

        if (kb + 2 < T) {
            int nb3 = buf + 2; if (nb3 >= 3) nb3 -= 3;
            const uint32_t* src = gb + (size_t)(kb + 2)*KWORDS;
            uint32_t dstb = sb + (QLW + nb3*KWORDS)*4;
#pragma unroll
            for (int j = 0; j < 8; j++) {
                int i = j*256 + tid;
                if (i < 1920) CP16(dstb + i*16, src + i*4);
            }
            CP_COMMIT();
        }

        const uint32_t* Kh = KB0 + buf*KWORDS;
        const uint32_t* Kl = Kh + SEGW;
        const uint32_t* Vt = Kh + 2*SEGW;

        // ---- 4-chunk software pipeline: S(c+1) before softmax+PV(c) ----
        float sA[2][4], sB[2][4];
        CHUNK_S(sA, 0);
#pragma unroll
        for (int ch = 0; ch < 4; ch++) {
            float (*s_cur)[4] = (ch & 1) ? sB : sA;
            float (*s_nxt)[4] = (ch & 1) ? sA : sB;
            if (ch < 3) CHUNK_S(s_nxt, ch + 1);

            // online softmax for this 16-key chunk
            float mx0 = fmaxf(fmaxf(s_cur[0][0], s_cur[0][1]), fmaxf(s_cur[1][0], s_cur[1][1]));
            float mx1 = fmaxf(fmaxf(s_cur[0][2], s_cur[0][3]), fmaxf(s_cur[1][2], s_cur[1][3]));
            mx0 = fmaxf(mx0, __shfl_xor_sync(0xffffffffu, mx0, 1));
            mx0 = fmaxf(mx0, __shfl_xor_sync(0xffffffffu, mx0, 2));
            mx1 = fmaxf(mx1, __shfl_xor_sync(0xffffffffu, mx1, 1));
            mx1 = fmaxf(mx1, __shfl_xor_sync(0xffffffffu, mx1, 2));
            float mn0 = fmaxf(m0, mx0), mn1 = fmaxf(m1, mx1);
            bool chg = (mn0 != m0) || (mn1 != m1);
            if (__any_sync(0xffffffffu, chg)) {
                float c0f = __expf(m0 - mn0), c1f = __expf(m1 - mn1);
                d_l[0] *= c0f; d_l[1] *= c0f; d_l[2] *= c1f; d_l[3] *= c1f;
#pragma unroll
                for (int nb = 0; nb < 8; nb++) {
                    o[nb][0] *= c0f; o[nb][1] *= c0f;
                    o[nb][2] *= c1f; o[nb][3] *= c1f;
                }
            }
            m0 = mn0; m1 = mn1;

            // exp (f16x2 ex2), l via ones-MMA, PV
            float ml0 = mn0 * L2E, ml1 = mn1 * L2E;
            float t0 = fmaf(s_cur[0][0], L2E, -ml0);
            float t1 = fmaf(s_cur[0][1], L2E, -ml0);
            float t2 = fmaf(s_cur[0][2], L2E, -ml1);
            float t3 = fmaf(s_cur[0][3], L2E, -ml1);
            uint32_t a0 = packh(t0, t1);
            uint32_t a1 = packh(t2, t3);
            t0 = fmaf(s_cur[1][0], L2E, -ml0);
            t1 = fmaf(s_cur[1][1], L2E, -ml0);
            t2 = fmaf(s_cur[1][2], L2E, -ml1);
            t3 = fmaf(s_cur[1][3], L2E, -ml1);
            uint32_t a2 = packh(t0, t1);
            uint32_t a3 = packh(t2, t3);
            HEX2(a0); HEX2(a1); HEX2(a2); HEX2(a3);
            mma16(d_l, a0, a1, a2, a3, bones, bones);
#pragma unroll
            for (int nb = 0; nb < 8; nb++) {
                uint2 bb = *(const uint2*)(Vt + (nb*8+g)*BSTR + ch*8 + 2*q4);
                mma16(o[nb], a0, a1, a2, a3, bb.x, bb.y);
            }
        }
        buf++; if (buf == 3) buf = 0;
    }

    // ---- epilogue ----
    float lr0 = __shfl_sync(0xffffffffu, d_l[0], lane & 28);
    float lr1 = __shfl_sync(0xffffffffu, d_l[2], lane & 28);
    float i0 = 1.f / lr0, i1 = 1.f / lr1;
    float* ob = outp + (size_t)b * 64 * N;
    const int q0 = qt * 128;
#pragma unroll
    for (int nb = 0; nb < 8; nb++) {
        int cix = nb*8 + 2*q4;
        ob[(size_t) cix   *N + q0 + r0    ] = o[nb][0]*i0;
        ob[(size_t)(cix+1)*N + q0 + r0    ] = o[nb][1]*i0;
        ob[(size_t) cix   *N + q0 + r0 + 8] = o[nb][2]*i1;
        ob[(size_t)(cix+1)*N + q0 + r0 + 8] = o[nb][3]*i1;
    }
}

// ---------------- Stage 3: bilinear upsample + residual ----------------
__device__ __forceinline__ float bilin(const float* __restrict__ p, int hp,
                                       int y, int x, float inv_s) {
    float sy = (y + 0.5f)*inv_s - 0.5f;
    float sx = (x + 0.5f)*inv_s - 0.5f;
    float fy = floorf(sy), fx = floorf(sx);
    float wy = sy - fy, wx = sx - fx;
    int y0 = max((int)fy, 0), y1 = min((int)fy + 1, hp-1);
    int x0 = max((int)fx, 0), x1 = min((int)fx + 1, hp-1);
    float a = p[y0*hp + x0], b2 = p[y0*hp + x1];
    float c2 = p[y1*hp + x0], d2 = p[y1*hp + x1];
    return (a*(1.f-wx) + b2*wx)*(1.f-wy) + (c2*(1.f-wx) + d2*wx)*wy;
}

__global__ void __launch_bounds__(256) final_kernel(const float* __restrict__ x,
                                                    float* __restrict__ out) {
    int idx = blockIdx.x*256 + threadIdx.x;
    if (idx >= BB*CC*HH*WW) return;
    int xx = idx & 63, yy = (idx >> 6) & 63, bc = idx >> 12;
    float v = x[idx] + g_o1[idx];
    v += bilin(g_o2 + bc*1024, 32, yy, xx, 0.5f);
    v += bilin(g_o4 + bc*256,  16, yy, xx, 0.25f);
    out[idx] = v;
}

// ---------------- launch ----------------
extern "C" void kernel_launch(void* const* d_in, const int* in_sizes, int n_in,
                              void* d_out, int out_size) {
    const float* x = (const float*)d_in[0];
    const float* w = (const float*)d_in[1];
    float* out = (float*)d_out;

    cudaFuncSetAttribute(attn_fused, cudaFuncAttributeMaxDynamicSharedMemorySize, ATTN_SMEM);
    cudaFuncSetAttribute(convmma_kernel, cudaFuncAttributeMaxDynamicSharedMemorySize, CONV_SMEM);

    wpack_kernel<<<72, 256>>>(w);
    convmma_kernel<<<dim3(64, 8), 128, CONV_SMEM>>>(x);
    poolpack_kernel<<<dim3(84, 8), 256>>>();
    attn_fused<<<dim3(42, 8), 256, ATTN_SMEM>>>();
    final_kernel<<<(BB*CC*HH*WW + 255)/256, 256>>>(x, out);
}

// round 15
// speedup vs baseline: 1.0366x; 1.0366x over previous
#include <cuda_runtime.h>
#include <cuda_fp16.h>
#include <cstdint>
#include <math.h>

#define BB 8
#define CC 64
#define HH 64
#define WW 64

#define BSTR 40              // words per row in fp16x2 tiles
#define SEGW 2560            // 64 rows * BSTR words  (10KB)
#define KWORDS (3*SEGW)      // packed tile: Kh | Kl | Vt (30KB)

// ---------------- scratch (static device globals; no allocation) ----------------
__device__ float g_feat[BB*CC*HH*WW];      // [B][C][H][W]
__device__ uint32_t g_wp[9*2*SEGW];        // packed conv weights per tap: [tap][Wh|Wl*2048]
__device__ uint32_t g_p1[BB*64*KWORDS];    // packed fp16 tiles per scale
__device__ uint32_t g_p2[BB*16*KWORDS];
__device__ uint32_t g_p4[BB*4*KWORDS];
__device__ float g_o1[BB*CC*4096];         // attention outputs [B][C][n]
__device__ float g_o2[BB*CC*1024];
__device__ float g_o4[BB*CC*256];

__device__ __forceinline__ uint32_t packh(float lo, float hi) {  // word = {hi16, lo16}
    uint32_t r;
    asm("cvt.rn.f16x2.f32 %0, %1, %2;" : "=r"(r) : "f"(hi), "f"(lo));
    return r;
}
__device__ __forceinline__ int islot(int u) { return 2*(u & 3) + (u >> 2); }
__device__ __forceinline__ uint32_t smem_u32(const void* p) {
    uint32_t a;
    asm("{ .reg .u64 t; cvta.to.shared.u64 t, %1; cvt.u32.u64 %0, t; }" : "=r"(a) : "l"(p));
    return a;
}
#define CP16(dst, src) asm volatile("cp.async.cg.shared.global [%0], [%1], 16;" :: "r"(dst), "l"(src))
#define CP_COMMIT()    asm volatile("cp.async.commit_group;" ::: "memory")
#define CP_WAIT1()     asm volatile("cp.async.wait_group 1;" ::: "memory")
#define CP_WAIT0()     asm volatile("cp.async.wait_group 0;" ::: "memory")
#define HEX2(x)        asm("ex2.approx.f16x2 %0, %0;" : "+r"(x))

// m16n8k16 fp16 MMA, row.col, f32 accumulate-in-place
__device__ __forceinline__ void mma16(float* d, uint32_t a0, uint32_t a1, uint32_t a2,
                                      uint32_t a3, uint32_t b0, uint32_t b1) {
    asm volatile("mma.sync.aligned.m16n8k16.row.col.f32.f16.f16.f32 "
        "{%0,%1,%2,%3}, {%4,%5,%6,%7}, {%8,%9}, {%0,%1,%2,%3};"
        : "+f"(d[0]), "+f"(d[1]), "+f"(d[2]), "+f"(d[3])
        : "r"(a0), "r"(a1), "r"(a2), "r"(a3), "r"(b0), "r"(b1));
}

// ---------------- Stage 0: weight pack (fold Laplacian, split fp16, tile layout) ----------------
__global__ void __launch_bounds__(256) wpack_kernel(const float* __restrict__ w) {
    int i = blockIdx.x*256 + threadIdx.x;          // 9*64*32 = 18432
    if (i >= 9*64*32) return;
    const float lapv[9] = {0.f, 1.f, 0.f, 1.f, -4.f, 1.f, 0.f, 1.f, 0.f};
    int tap = i >> 11;
    int rem = i & 2047;
    int oc = rem >> 5, u = rem & 31;
    int ic0 = 2*u, ic1 = 2*u + 1;
    float a = w[oc*576 + ic0*9 + tap] + ((oc == ic0) ? lapv[tap] : 0.f);
    float c = w[oc*576 + ic1*9 + tap] + ((oc == ic1) ? lapv[tap] : 0.f);
    uint32_t h = packh(a, c);
    float2 fh = __half22float2(*(const __half2*)&h);
    uint32_t l = packh((a - fh.x)*2048.f, (c - fh.y)*2048.f);
    int slot = tap*2*SEGW + oc*BSTR + (u >> 3)*8 + islot(u & 7);
    g_wp[slot]        = h;
    g_wp[slot + SEGW] = l;
}

// ---------------- Stage 1: conv as split-fp16 implicit GEMM on tensor cores ----------------
// Double-buffered W taps (2 x 20KB) -> 74.6KB smem -> 3 CTAs/SM, single-wave grid.
#define XROWS 108
#define XW (XROWS*BSTR)
#define CONV_SMEM ((2*XW + 2*2*SEGW) * 4)

__global__ void __launch_bounds__(128, 3) convmma_kernel(const float* __restrict__ x) {
    const int t = blockIdx.x;
    const int b = blockIdx.y;
    const int ty = t >> 2, tx = t & 3;
    extern __shared__ uint32_t cs[];
    uint32_t* Xh = cs;
    uint32_t* Xl = cs + XW;
    uint32_t* WB = cs + 2*XW;                  // 2 buffers of 5120 words
    const int tid  = threadIdx.x;
    const int w    = tid >> 5;
    const int lane = tid & 31;
    const int g    = lane >> 2;
    const int q4   = lane & 3;
    const uint32_t sb = smem_u32(cs);

    // prefetch W tap 0
#pragma unroll
    for (int j = 0; j < 10; j++) {
        int i = j*128 + tid;
        CP16(sb + (2*XW + i*4)*4, g_wp + i*4);
    }
    CP_COMMIT();

    // stage X halo: 108 rows x 32 ch-pair words, split hi / lo*2048
#pragma unroll
    for (int j = 0; j < 27; j++) {
        int wi = j*128 + tid;
        int u = wi / 108, r = wi - u*108;
        int hy = r / 18, hx = r - hy*18;
        int gy = ty*4 - 1 + hy, gx = tx*16 - 1 + hx;
        float a = 0.f, c = 0.f;
        if (gy >= 0 && gy < 64 && gx >= 0 && gx < 64) {
            const float* p = x + (((size_t)b*64 + 2*u)*4096 + gy*64 + gx);
            a = p[0]; c = p[4096];
        }
        uint32_t h = packh(a, c);
        float2 fh = __half22float2(*(const __half2*)&h);
        uint32_t l = packh((a - fh.x)*2048.f, (c - fh.y)*2048.f);
        int slot = r*BSTR + (u >> 3)*8 + islot(u & 7);
        Xh[slot] = h;
        Xl[slot] = l;
    }

    float o[8][4], c[8][4];
#pragma unroll
    for (int nb = 0; nb < 8; nb++)
#pragma unroll
        for (int j = 0; j < 4; j++) { o[nb][j] = 0.f; c[nb][j] = 0.f; }

    for (int tap = 0; tap < 9; tap++) {
        CP_WAIT0();
        __syncthreads();
        if (tap + 1 < 9) {                     // prefetch tap+1 into the other buffer
            int nb2 = (tap + 1) & 1;
#pragma unroll
            for (int j = 0; j < 10; j++) {
                int i = j*128 + tid;
                CP16(sb + (2*XW + nb2*2*SEGW + i*4)*4, g_wp + (size_t)(tap + 1)*2*SEGW + i*4);
            }
            CP_COMMIT();
        }
        const uint32_t* Wh = WB + (tap & 1)*2*SEGW;
        const uint32_t* Wl = Wh + SEGW;
        const int dy = tap / 3, dx = tap - dy*3;
        const int rA = (w + dy)*18 + g + dx;

        uint2 ahA[4], ahB[4], alA[4], alB[4];
#pragma unroll
        for (int ks = 0; ks < 4; ks++) {
            ahA[ks] = *(const uint2*)(Xh +  rA     *BSTR + ks*8 + 2*q4);
            ahB[ks] = *(const uint2*)(Xh + (rA+8)  *BSTR + ks*8 + 2*q4);
            alA[ks] = *(const uint2*)(Xl +  rA     *BSTR + ks*8 + 2*q4);
            alB[ks] = *(const uint2*)(Xl + (rA+8)  *BSTR + ks*8 + 2*q4);
        }
#pragma unroll
        for (int ks = 0; ks < 4; ks++) {
#pragma unroll
            for (int nb = 0; nb < 8; nb++) {
                uint2 bh = *(const uint2*)(Wh + (nb*8+g)*BSTR + ks*8 + 2*q4);
                uint2 bl = *(const uint2*)(Wl + (nb*8+g)*BSTR + ks*8 + 2*q4);
                mma16(o[nb], ahA[ks].x, ahB[ks].x, ahA[ks].y, ahB[ks].y, bh.x, bh.y);
                mma16(c[nb], ahA[ks].x, ahB[ks].x, ahA[ks].y, ahB[ks].y, bl.x, bl.y);
                mma16(c[nb], alA[ks].x, alB[ks].x, alA[ks].y, alB[ks].y, bh.x, bh.y);
            }
        }
        __syncthreads();   // all reads of this W buffer done before next prefetch overwrites
    }

    const int y = ty*4 + w;
    float* fb = g_feat + (((size_t)b*64)*64 + y)*64 + tx*16;
#pragma unroll
    for (int nb = 0; nb < 8; nb++) {
        int oc = nb*8 + 2*q4;
        fb[(size_t) oc   *4096 + g    ] = fmaf(c[nb][0], 4.8828125e-4f, o[nb][0]);
        fb[(size_t)(oc+1)*4096 + g    ] = fmaf(c[nb][1], 4.8828125e-4f, o[nb][1]);
        fb[(size_t) oc   *4096 + g + 8] = fmaf(c[nb][2], 4.8828125e-4f, o[nb][2]);
        fb[(size_t)(oc+1)*4096 + g + 8] = fmaf(c[nb][3], 4.8828125e-4f, o[nb][3]);
    }
}

// ---------------- Stage 2a: fused pool + split/pack ----------------
__global__ void __launch_bounds__(256) poolpack_kernel() {
    const int t = blockIdx.x;
    const int b = blockIdx.y;
    int S, tt, N; uint32_t* gpack;
    if (t < 64)      { S = 1; tt = t;      gpack = g_p1; N = 4096; }
    else if (t < 80) { S = 2; tt = t - 64; gpack = g_p2; N = 1024; }
    else             { S = 4; tt = t - 80; gpack = g_p4; N = 256;  }
    const int WP = 64 / S;
    const float inv = 1.f / (float)(S*S);
    __shared__ float tile[64][65];
    const float* fb = g_feat + (size_t)b*CC*HH*WW;
    const int tid = threadIdx.x;

    for (int i = tid; i < 4096; i += 256) {
        int ch = i >> 6, key = i & 63;
        int n = tt*64 + key;
        int ny = n / WP, nx = n % WP;
        const float* p = fb + ch*4096 + (ny*S)*64 + nx*S;
        float s = 0.f;
        for (int dy = 0; dy < S; dy++)
            for (int dx = 0; dx < S; dx++)
                s += p[dy*64 + dx];
        tile[key][ch] = s * inv;
    }
    __syncthreads();

    uint32_t* gp = gpack + ((size_t)b*(N >> 6) + tt) * KWORDS;
#pragma unroll
    for (int j = 0; j < 8; j++) {
        int wi = j*256 + tid;
        int r = wi >> 5, u = wi & 31;
        float a = tile[r][2*u];
        float c = tile[r][2*u + 1];
        uint32_t h = packh(a, c);
        float2 fh = __half22float2(*(const __half2*)&h);
        uint32_t l = packh((a - fh.x)*2048.f, (c - fh.y)*2048.f);
        int slot = r*BSTR + (u >> 3)*8 + islot(u & 7);
        gp[slot]        = h;
        gp[SEGW + slot] = l;
    }
#pragma unroll
    for (int j = 0; j < 8; j++) {
        int wi = j*256 + tid;
        int ch = wi >> 5, lwv = wi & 31;
        float a = tile[2*lwv    ][ch];
        float c = tile[2*lwv + 1][ch];
        gp[2*SEGW + ch*BSTR + (lwv >> 3)*8 + islot(lwv & 7)] = packh(a, c);
    }
}

// ---------------- Stage 2b: fused flash attention, split-tile softmax pipelining (R13) ----------------
#define QLW 5120
#define ATTN_SMEM ((QLW + 3*KWORDS) * 4)

__global__ void __launch_bounds__(256, 2) attn_fused() {
    const int qtsel = blockIdx.x;
    const int b = blockIdx.y;
    int N, qt;
    const uint32_t* gpack;
    float* outp;
    if (qtsel < 32)      { N = 4096; qt = qtsel;      gpack = g_p1; outp = g_o1; }
    else if (qtsel < 40) { N = 1024; qt = qtsel - 32; gpack = g_p2; outp = g_o2; }
    else                 { N = 256;  qt = qtsel - 40; gpack = g_p4; outp = g_o4; }
    const int T = N >> 6;

    extern __shared__ uint32_t smw[];
    uint32_t* Ql = smw;
    uint32_t* KB0 = smw + QLW;

    const int tid  = threadIdx.x;
    const int w    = tid >> 5;
    const int lane = tid & 31;
    const int g    = lane >> 2;
    const int q4   = lane & 3;
    const int r0   = w*16 + g;
    const uint32_t* gb = gpack + (size_t)b*T*KWORDS;
    const uint32_t sb = smem_u32(smw);
    const uint32_t bones = (g == 0) ? 0x3C003C00u : 0u;

    // ---- preload: Qh -> KB0 (staging), Ql -> Ql region ----
#pragma unroll
    for (int j = 0; j < 10; j++) {
        int i = j*256 + tid;
        int seg = i / 640;
        int s2 = seg >> 1, p = seg & 1;
        int fo = (i - seg*640) * 4;
        const uint32_t* src = gb + (size_t)(2*qt + p)*KWORDS + s2*SEGW + fo;
        int dst = (s2 ? 0 : QLW) + p*SEGW + fo;
        CP16(sb + dst*4, src);
    }
    CP_COMMIT();
    CP_WAIT0();
    __syncthreads();

    uint2 qA[4], qB[4];
#pragma unroll
    for (int ks = 0; ks < 4; ks++) {
        qA[ks] = *(const uint2*)(KB0 +  r0    *BSTR + ks*8 + 2*q4);
        qB[ks] = *(const uint2*)(KB0 + (r0+8) *BSTR + ks*8 + 2*q4);
    }
    __syncthreads();

#pragma unroll
    for (int p = 0; p < 2; p++) {
        const uint32_t* src = gb + (size_t)p*KWORDS;
        uint32_t dstb = sb + (QLW + p*KWORDS)*4;
#pragma unroll
        for (int j = 0; j < 8; j++) {
            int i = j*256 + tid;
            if (i < 1920) CP16(dstb + i*16, src + i*4);
        }
        CP_COMMIT();
    }

    float m0 = -3.0e38f, m1 = -3.0e38f;
    float d_l[4] = {0.f, 0.f, 0.f, 0.f};
    float o[8][4];
#pragma unroll
    for (int nb = 0; nb < 8; nb++)
#pragma unroll
        for (int j = 0; j < 4; j++) o[nb][j] = 0.f;

    const float L2E = 1.4426950408889634f;
    int buf = 0;
    for (int kb = 0; kb < T; kb++) {
        if (kb == T - 1) CP_WAIT0(); else CP_WAIT1();
        __syncthreads();

        if (kb + 2 < T) {
            int nb3 = buf + 2; if (nb3 >= 3) nb3 -= 3;
            const uint32_t* src = gb + (size_t)(kb + 2)*KWORDS;
            uint32_t dstb = sb + (QLW + nb3*KWORDS)*4;
#pragma unroll
            for (int j = 0; j < 8; j++) {
                int i = j*256 + tid;
                if (i < 1920) CP16(dstb + i*16, src + i*4);
            }
            CP_COMMIT();
        }

        const uint32_t* Kh = KB0 + buf*KWORDS;
        const uint32_t* Kl = Kh + SEGW;
        const uint32_t* Vt = Kh + 2*SEGW;

        // ---- two independent 32-key half-tiles: S -> softmax -> PV per half ----
#pragma unroll
        for (int h = 0; h < 2; h++) {
            float s[4][4];
#pragma unroll
            for (int nb = 0; nb < 4; nb++)
#pragma unroll
                for (int j = 0; j < 4; j++) s[nb][j] = 0.f;

            // pass 0: Qh(regs) * Kl
#pragma unroll
            for (int ks = 0; ks < 4; ks++) {
#pragma unroll
                for (int nb = 0; nb < 4; nb++) {
                    uint2 bb = *(const uint2*)(Kl + ((4*h+nb)*8+g)*BSTR + ks*8 + 2*q4);
                    mma16(s[nb], qA[ks].x, qB[ks].x, qA[ks].y, qB[ks].y, bb.x, bb.y);
                }
            }
            // pass 1: Ql(smem) * Kh
#pragma unroll
            for (int ks = 0; ks < 4; ks++) {
                uint2 aA = *(const uint2*)(Ql +  r0    *BSTR + ks*8 + 2*q4);
                uint2 aB = *(const uint2*)(Ql + (r0+8) *BSTR + ks*8 + 2*q4);
#pragma unroll
                for (int nb = 0; nb < 4; nb++) {
                    uint2 bb = *(const uint2*)(Kh + ((4*h+nb)*8+g)*BSTR + ks*8 + 2*q4);
                    mma16(s[nb], aA.x, aB.x, aA.y, aB.y, bb.x, bb.y);
                }
            }
#pragma unroll
            for (int nb = 0; nb < 4; nb++)
#pragma unroll
                for (int j = 0; j < 4; j++) s[nb][j] *= 4.8828125e-4f;   // /2048
            // pass 2: exact hh
#pragma unroll
            for (int ks = 0; ks < 4; ks++) {
#pragma unroll
                for (int nb = 0; nb < 4; nb++) {
                    uint2 bb = *(const uint2*)(Kh + ((4*h+nb)*8+g)*BSTR + ks*8 + 2*q4);
                    mma16(s[nb], qA[ks].x, qB[ks].x, qA[ks].y, qB[ks].y, bb.x, bb.y);
                }
            }

            // ---- online softmax for this half ----
            float mx0 = -3.0e38f, mx1 = -3.0e38f;
#pragma unroll
            for (int nb = 0; nb < 4; nb++) {
                mx0 = fmaxf(mx0, fmaxf(s[nb][0], s[nb][1]));
                mx1 = fmaxf(mx1, fmaxf(s[nb][2], s[nb][3]));
            }
            mx0 = fmaxf(mx0, __shfl_xor_sync(0xffffffffu, mx0, 1));
            mx0 = fmaxf(mx0, __shfl_xor_sync(0xffffffffu, mx0, 2));
            mx1 = fmaxf(mx1, __shfl_xor_sync(0xffffffffu, mx1, 1));
            mx1 = fmaxf(mx1, __shfl_xor_sync(0xffffffffu, mx1, 2));
            float mn0 = fmaxf(m0, mx0), mn1 = fmaxf(m1, mx1);
            bool chg = (mn0 != m0) || (mn1 != m1);
            if (__any_sync(0xffffffffu, chg)) {
                float c0f = __expf(m0 - mn0), c1f = __expf(m1 - mn1);
                d_l[0] *= c0f; d_l[1] *= c0f; d_l[2] *= c1f; d_l[3] *= c1f;
#pragma unroll
                for (int nb = 0; nb < 8; nb++) {
                    o[nb][0] *= c0f; o[nb][1] *= c0f;
                    o[nb][2] *= c1f; o[nb][3] *= c1f;
                }
            }
            m0 = mn0; m1 = mn1;

            // ---- exp (f16x2 ex2) + l via ones-MMA + PV ----
            float ml0 = mn0 * L2E, ml1 = mn1 * L2E;
#pragma unroll
            for (int k = 0; k < 2; k++) {
                float t0 = fmaf(s[2*k  ][0], L2E, -ml0);
                float t1 = fmaf(s[2*k  ][1], L2E, -ml0);
                float t2 = fmaf(s[2*k  ][2], L2E, -ml1);
                float t3 = fmaf(s[2*k  ][3], L2E, -ml1);
                uint32_t a0 = packh(t0, t1);
                uint32_t a1 = packh(t2, t3);
                t0 = fmaf(s[2*k+1][0], L2E, -ml0);
                t1 = fmaf(s[2*k+1][1], L2E, -ml0);
                t2 = fmaf(s[2*k+1][2], L2E, -ml1);
                t3 = fmaf(s[2*k+1][3], L2E, -ml1);
                uint32_t a2 = packh(t0, t1);
                uint32_t a3 = packh(t2, t3);
                HEX2(a0); HEX2(a1); HEX2(a2); HEX2(a3);
                mma16(d_l, a0, a1, a2, a3, bones, bones);
#pragma unroll
                for (int nb = 0; nb < 8; nb++) {
                    uint2 bb = *(const uint2*)(Vt + (nb*8+g)*BSTR + (2*h+k)*8 + 2*q4);
                    mma16(o[nb], a0, a1, a2, a3, bb.x, bb.y);
                }
            }
        }
        buf++; if (buf == 3) buf = 0;
    }

    // ---- epilogue ----
    float lr0 = __shfl_sync(0xffffffffu, d_l[0], lane & 28);
    float lr1 = __shfl_sync(0xffffffffu, d_l[2], lane & 28);
    float i0 = 1.f / lr0, i1 = 1.f / lr1;
    float* ob = outp + (size_t)b * 64 * N;
    const int q0 = qt * 128;
#pragma unroll
    for (int nb = 0; nb < 8; nb++) {
        int cix = nb*8 + 2*q4;
        ob[(size_t) cix   *N + q0 + r0    ] = o[nb][0]*i0;
        ob[(size_t)(cix+1)*N + q0 + r0    ] = o[nb][1]*i0;
        ob[(size_t) cix   *N + q0 + r0 + 8] = o[nb][2]*i1;
        ob[(size_t)(cix+1)*N + q0 + r0 + 8] = o[nb][3]*i1;
    }
}

// ---------------- Stage 3: bilinear upsample + residual ----------------
__device__ __forceinline__ float bilin(const float* __restrict__ p, int hp,
                                       int y, int x, float inv_s) {
    float sy = (y + 0.5f)*inv_s - 0.5f;
    float sx = (x + 0.5f)*inv_s - 0.5f;
    float fy = floorf(sy), fx = floorf(sx);
    float wy = sy - fy, wx = sx - fx;
    int y0 = max((int)fy, 0), y1 = min((int)fy + 1, hp-1);
    int x0 = max((int)fx, 0), x1 = min((int)fx + 1, hp-1);
    float a = p[y0*hp + x0], b2 = p[y0*hp + x1];
    float c2 = p[y1*hp + x0], d2 = p[y1*hp + x1];
    return (a*(1.f-wx) + b2*wx)*(1.f-wy) + (c2*(1.f-wx) + d2*wx)*wy;
}

__global__ void __launch_bounds__(256) final_kernel(const float* __restrict__ x,
                                                    float* __restrict__ out) {
    int idx = blockIdx.x*256 + threadIdx.x;
    if (idx >= BB*CC*HH*WW) return;
    int xx = idx & 63, yy = (idx >> 6) & 63, bc = idx >> 12;
    float v = x[idx] + g_o1[idx];
    v += bilin(g_o2 + bc*1024, 32, yy, xx, 0.5f);
    v += bilin(g_o4 + bc*256,  16, yy, xx, 0.25f);
    out[idx] = v;
}

// ---------------- launch ----------------
extern "C" void kernel_launch(void* const* d_in, const int* in_sizes, int n_in,
                              void* d_out, int out_size) {
    const float* x = (const float*)d_in[0];
    const float* w = (const float*)d_in[1];
    float* out = (float*)d_out;

    cudaFuncSetAttribute(attn_fused, cudaFuncAttributeMaxDynamicSharedMemorySize, ATTN_SMEM);
    cudaFuncSetAttribute(convmma_kernel, cudaFuncAttributeMaxDynamicSharedMemorySize, CONV_SMEM);

    wpack_kernel<<<72, 256>>>(w);
    convmma_kernel<<<dim3(64, 8), 128, CONV_SMEM>>>(x);
    poolpack_kernel<<<dim3(84, 8), 256>>>();
    attn_fused<<<dim3(42, 8), 256, ATTN_SMEM>>>();
    final_kernel<<<(BB*CC*HH*WW + 255)/256, 256>>>(x, out);
}

// round 16
// speedup vs baseline: 1.0483x; 1.0113x over previous
#include <cuda_runtime.h>
#include <cuda_fp16.h>
#include <cstdint>
#include <math.h>

#define BB 8
#define CC 64
#define HH 64
#define WW 64

#define BSTR 40              // words per row in fp16x2 tiles
#define SEGW 2560            // 64 rows * BSTR words  (10KB)
#define KWORDS (3*SEGW)      // packed tile: Kh | Kl | Vt (30KB)

// ---------------- scratch (static device globals; no allocation) ----------------
__device__ float g_feat[BB*CC*HH*WW];      // [B][C][H][W]
__device__ uint32_t g_wp[9*2*SEGW];        // packed conv weights per tap: [tap][Wh|Wl*2048]
__device__ uint32_t g_p1[BB*64*KWORDS];    // packed fp16 tiles per scale
__device__ uint32_t g_p2[BB*16*KWORDS];
__device__ uint32_t g_p4[BB*4*KWORDS];
__device__ float g_o1[BB*CC*4096];         // attention outputs [B][C][n]
__device__ float g_o2[BB*CC*1024];
__device__ float g_o4[BB*CC*256];

__device__ __forceinline__ uint32_t packh(float lo, float hi) {  // word = {hi16, lo16}
    uint32_t r;
    asm("cvt.rn.f16x2.f32 %0, %1, %2;" : "=r"(r) : "f"(hi), "f"(lo));
    return r;
}
__device__ __forceinline__ int islot(int u) { return 2*(u & 3) + (u >> 2); }
__device__ __forceinline__ uint32_t smem_u32(const void* p) {
    uint32_t a;
    asm("{ .reg .u64 t; cvta.to.shared.u64 t, %1; cvt.u32.u64 %0, t; }" : "=r"(a) : "l"(p));
    return a;
}
#define CP16(dst, src) asm volatile("cp.async.cg.shared.global [%0], [%1], 16;" :: "r"(dst), "l"(src))
#define CP_COMMIT()    asm volatile("cp.async.commit_group;" ::: "memory")
#define CP_WAIT1()     asm volatile("cp.async.wait_group 1;" ::: "memory")
#define CP_WAIT0()     asm volatile("cp.async.wait_group 0;" ::: "memory")
#define HEX2(x)        asm("ex2.approx.f16x2 %0, %0;" : "+r"(x))

// m16n8k16 fp16 MMA, row.col, f32 accumulate-in-place
__device__ __forceinline__ void mma16(float* d, uint32_t a0, uint32_t a1, uint32_t a2,
                                      uint32_t a3, uint32_t b0, uint32_t b1) {
    asm volatile("mma.sync.aligned.m16n8k16.row.col.f32.f16.f16.f32 "
        "{%0,%1,%2,%3}, {%4,%5,%6,%7}, {%8,%9}, {%0,%1,%2,%3};"
        : "+f"(d[0]), "+f"(d[1]), "+f"(d[2]), "+f"(d[3])
        : "r"(a0), "r"(a1), "r"(a2), "r"(a3), "r"(b0), "r"(b1));
}

// ---------------- Stage 0: weight pack (fold Laplacian, split fp16, tile layout) ----------------
__global__ void __launch_bounds__(256) wpack_kernel(const float* __restrict__ w) {
    int i = blockIdx.x*256 + threadIdx.x;          // 9*64*32 = 18432
    if (i >= 9*64*32) return;
    const float lapv[9] = {0.f, 1.f, 0.f, 1.f, -4.f, 1.f, 0.f, 1.f, 0.f};
    int tap = i >> 11;
    int rem = i & 2047;
    int oc = rem >> 5, u = rem & 31;
    int ic0 = 2*u, ic1 = 2*u + 1;
    float a = w[oc*576 + ic0*9 + tap] + ((oc == ic0) ? lapv[tap] : 0.f);
    float c = w[oc*576 + ic1*9 + tap] + ((oc == ic1) ? lapv[tap] : 0.f);
    uint32_t h = packh(a, c);
    float2 fh = __half22float2(*(const __half2*)&h);
    uint32_t l = packh((a - fh.x)*2048.f, (c - fh.y)*2048.f);
    int slot = tap*2*SEGW + oc*BSTR + (u >> 3)*8 + islot(u & 7);
    g_wp[slot]        = h;
    g_wp[slot + SEGW] = l;
}

// ---------------- Stage 1: conv as split-fp16 implicit GEMM on tensor cores (R13 config) ----------------
#define XROWS 108
#define XW (XROWS*BSTR)
#define CONV_SMEM ((2*XW + 3*2*SEGW) * 4)

__global__ void __launch_bounds__(128, 2) convmma_kernel(const float* __restrict__ x) {
    const int t = blockIdx.x;
    const int b = blockIdx.y;
    const int ty = t >> 2, tx = t & 3;
    extern __shared__ uint32_t cs[];
    uint32_t* Xh = cs;
    uint32_t* Xl = cs + XW;
    uint32_t* WB = cs + 2*XW;
    const int tid  = threadIdx.x;
    const int w    = tid >> 5;
    const int lane = tid & 31;
    const int g    = lane >> 2;
    const int q4   = lane & 3;
    const uint32_t sb = smem_u32(cs);

#pragma unroll
    for (int p = 0; p < 2; p++) {
#pragma unroll
        for (int j = 0; j < 10; j++) {
            int i = j*128 + tid;
            CP16(sb + (2*XW + p*2*SEGW + i*4)*4, g_wp + p*2*SEGW + i*4);
        }
        CP_COMMIT();
    }

#pragma unroll
    for (int j = 0; j < 27; j++) {
        int wi = j*128 + tid;
        int u = wi / 108, r = wi - u*108;
        int hy = r / 18, hx = r - hy*18;
        int gy = ty*4 - 1 + hy, gx = tx*16 - 1 + hx;
        float a = 0.f, c = 0.f;
        if (gy >= 0 && gy < 64 && gx >= 0 && gx < 64) {
            const float* p = x + (((size_t)b*64 + 2*u)*4096 + gy*64 + gx);
            a = p[0]; c = p[4096];
        }
        uint32_t h = packh(a, c);
        float2 fh = __half22float2(*(const __half2*)&h);
        uint32_t l = packh((a - fh.x)*2048.f, (c - fh.y)*2048.f);
        int slot = r*BSTR + (u >> 3)*8 + islot(u & 7);
        Xh[slot] = h;
        Xl[slot] = l;
    }

    float o[8][4], c[8][4];
#pragma unroll
    for (int nb = 0; nb < 8; nb++)
#pragma unroll
        for (int j = 0; j < 4; j++) { o[nb][j] = 0.f; c[nb][j] = 0.f; }

    for (int tap = 0; tap < 9; tap++) {
        if (tap == 8) CP_WAIT0(); else CP_WAIT1();
        __syncthreads();
        if (tap + 2 < 9) {
            int nb3 = (tap + 2) % 3;
#pragma unroll
            for (int j = 0; j < 10; j++) {
                int i = j*128 + tid;
                CP16(sb + (2*XW + nb3*2*SEGW + i*4)*4, g_wp + (size_t)(tap + 2)*2*SEGW + i*4);
            }
            CP_COMMIT();
        }
        const uint32_t* Wh = WB + (tap % 3)*2*SEGW;
        const uint32_t* Wl = Wh + SEGW;
        const int dy = tap / 3, dx = tap - dy*3;
        const int rA = (w + dy)*18 + g + dx;

        uint2 ahA[4], ahB[4], alA[4], alB[4];
#pragma unroll
        for (int ks = 0; ks < 4; ks++) {
            ahA[ks] = *(const uint2*)(Xh +  rA     *BSTR + ks*8 + 2*q4);
            ahB[ks] = *(const uint2*)(Xh + (rA+8)  *BSTR + ks*8 + 2*q4);
            alA[ks] = *(const uint2*)(Xl +  rA     *BSTR + ks*8 + 2*q4);
            alB[ks] = *(const uint2*)(Xl + (rA+8)  *BSTR + ks*8 + 2*q4);
        }
#pragma unroll
        for (int ks = 0; ks < 4; ks++) {
#pragma unroll
            for (int nb = 0; nb < 8; nb++) {
                uint2 bh = *(const uint2*)(Wh + (nb*8+g)*BSTR + ks*8 + 2*q4);
                uint2 bl = *(const uint2*)(Wl + (nb*8+g)*BSTR + ks*8 + 2*q4);
                mma16(o[nb], ahA[ks].x, ahB[ks].x, ahA[ks].y, ahB[ks].y, bh.x, bh.y);
                mma16(c[nb], ahA[ks].x, ahB[ks].x, ahA[ks].y, ahB[ks].y, bl.x, bl.y);
                mma16(c[nb], alA[ks].x, alB[ks].x, alA[ks].y, alB[ks].y, bh.x, bh.y);
            }
        }
    }

    const int y = ty*4 + w;
    float* fb = g_feat + (((size_t)b*64)*64 + y)*64 + tx*16;
#pragma unroll
    for (int nb = 0; nb < 8; nb++) {
        int oc = nb*8 + 2*q4;
        fb[(size_t) oc   *4096 + g    ] = fmaf(c[nb][0], 4.8828125e-4f, o[nb][0]);
        fb[(size_t)(oc+1)*4096 + g    ] = fmaf(c[nb][1], 4.8828125e-4f, o[nb][1]);
        fb[(size_t) oc   *4096 + g + 8] = fmaf(c[nb][2], 4.8828125e-4f, o[nb][2]);
        fb[(size_t)(oc+1)*4096 + g + 8] = fmaf(c[nb][3], 4.8828125e-4f, o[nb][3]);
    }
}

// ---------------- Stage 2a: fused pool + split/pack ----------------
__global__ void __launch_bounds__(256) poolpack_kernel() {
    const int t = blockIdx.x;
    const int b = blockIdx.y;
    int S, tt, N; uint32_t* gpack;
    if (t < 64)      { S = 1; tt = t;      gpack = g_p1; N = 4096; }
    else if (t < 80) { S = 2; tt = t - 64; gpack = g_p2; N = 1024; }
    else             { S = 4; tt = t - 80; gpack = g_p4; N = 256;  }
    const int WP = 64 / S;
    const float inv = 1.f / (float)(S*S);
    __shared__ float tile[64][65];
    const float* fb = g_feat + (size_t)b*CC*HH*WW;
    const int tid = threadIdx.x;

    for (int i = tid; i < 4096; i += 256) {
        int ch = i >> 6, key = i & 63;
        int n = tt*64 + key;
        int ny = n / WP, nx = n % WP;
        const float* p = fb + ch*4096 + (ny*S)*64 + nx*S;
        float s = 0.f;
        for (int dy = 0; dy < S; dy++)
            for (int dx = 0; dx < S; dx++)
                s += p[dy*64 + dx];
        tile[key][ch] = s * inv;
    }
    __syncthreads();

    uint32_t* gp = gpack + ((size_t)b*(N >> 6) + tt) * KWORDS;
#pragma unroll
    for (int j = 0; j < 8; j++) {
        int wi = j*256 + tid;
        int r = wi >> 5, u = wi & 31;
        float a = tile[r][2*u];
        float c = tile[r][2*u + 1];
        uint32_t h = packh(a, c);
        float2 fh = __half22float2(*(const __half2*)&h);
        uint32_t l = packh((a - fh.x)*2048.f, (c - fh.y)*2048.f);
        int slot = r*BSTR + (u >> 3)*8 + islot(u & 7);
        gp[slot]        = h;
        gp[SEGW + slot] = l;
    }
#pragma unroll
    for (int j = 0; j < 8; j++) {
        int wi = j*256 + tid;
        int ch = wi >> 5, lwv = wi & 31;
        float a = tile[2*lwv    ][ch];
        float c = tile[2*lwv + 1][ch];
        gp[2*SEGW + ch*BSTR + (lwv >> 3)*8 + islot(lwv & 7)] = packh(a, c);
    }
}

// ---------------- Stage 2b: fused flash attention, split-tile softmax pipelining (R13) ----------------
#define QLW 5120
#define ATTN_SMEM ((QLW + 3*KWORDS) * 4)

__global__ void __launch_bounds__(256, 2) attn_fused() {
    const int qtsel = blockIdx.x;
    const int b = blockIdx.y;
    int N, qt;
    const uint32_t* gpack;
    float* outp;
    if (qtsel < 32)      { N = 4096; qt = qtsel;      gpack = g_p1; outp = g_o1; }
    else if (qtsel < 40) { N = 1024; qt = qtsel - 32; gpack = g_p2; outp = g_o2; }
    else                 { N = 256;  qt = qtsel - 40; gpack = g_p4; outp = g_o4; }
    const int T = N >> 6;

    extern __shared__ uint32_t smw[];
    uint32_t* Ql = smw;
    uint32_t* KB0 = smw + QLW;

    const int tid  = threadIdx.x;
    const int w    = tid >> 5;
    const int lane = tid & 31;
    const int g    = lane >> 2;
    const int q4   = lane & 3;
    const int r0   = w*16 + g;
    const uint32_t* gb = gpack + (size_t)b*T*KWORDS;
    const uint32_t sb = smem_u32(smw);
    const uint32_t bones = (g == 0) ? 0x3C003C00u : 0u;

    // ---- preload: Qh -> KB0 (staging), Ql -> Ql region ----
#pragma unroll
    for (int j = 0; j < 10; j++) {
        int i = j*256 + tid;
        int seg = i / 640;
        int s2 = seg >> 1, p = seg & 1;
        int fo = (i - seg*640) * 4;
        const uint32_t* src = gb + (size_t)(2*qt + p)*KWORDS + s2*SEGW + fo;
        int dst = (s2 ? 0 : QLW) + p*SEGW + fo;
        CP16(sb + dst*4, src);
    }
    CP_COMMIT();
    CP_WAIT0();
    __syncthreads();

    uint2 qA[4], qB[4];
#pragma unroll
    for (int ks = 0; ks < 4; ks++) {
        qA[ks] = *(const uint2*)(KB0 +  r0    *BSTR + ks*8 + 2*q4);
        qB[ks] = *(const uint2*)(KB0 + (r0+8) *BSTR + ks*8 + 2*q4);
    }
    __syncthreads();

#pragma unroll
    for (int p = 0; p < 2; p++) {
        const uint32_t* src = gb + (size_t)p*KWORDS;
        uint32_t dstb = sb + (QLW + p*KWORDS)*4;
#pragma unroll
        for (int j = 0; j < 8; j++) {
            int i = j*256 + tid;
            if (i < 1920) CP16(dstb + i*16, src + i*4);
        }
        CP_COMMIT();
    }

    float m0 = -3.0e38f, m1 = -3.0e38f;
    float d_l[4] = {0.f, 0.f, 0.f, 0.f};
    float o[8][4];
#pragma unroll
    for (int nb = 0; nb < 8; nb++)
#pragma unroll
        for (int j = 0; j < 4; j++) o[nb][j] = 0.f;

    const float L2E = 1.4426950408889634f;
    int buf = 0;
    for (int kb = 0; kb < T; kb++) {
        if (kb == T - 1) CP_WAIT0(); else CP_WAIT1();
        __syncthreads();

        if (kb + 2 < T) {
            int nb3 = buf + 2; if (nb3 >= 3) nb3 -= 3;
            const uint32_t* src = gb + (size_t)(kb + 2)*KWORDS;
            uint32_t dstb = sb + (QLW + nb3*KWORDS)*4;
#pragma unroll
            for (int j = 0; j < 8; j++) {
                int i = j*256 + tid;
                if (i < 1920) CP16(dstb + i*16, src + i*4);
            }
            CP_COMMIT();
        }

        const uint32_t* Kh = KB0 + buf*KWORDS;
        const uint32_t* Kl = Kh + SEGW;
        const uint32_t* Vt = Kh + 2*SEGW;

        // ---- two independent 32-key half-tiles: S -> softmax -> PV per half ----
#pragma unroll
        for (int h = 0; h < 2; h++) {
            float s[4][4];
#pragma unroll
            for (int nb = 0; nb < 4; nb++)
#pragma unroll
                for (int j = 0; j < 4; j++) s[nb][j] = 0.f;

            // pass 0: Qh(regs) * Kl
#pragma unroll
            for (int ks = 0; ks < 4; ks++) {
#pragma unroll
                for (int nb = 0; nb < 4; nb++) {
                    uint2 bb = *(const uint2*)(Kl + ((4*h+nb)*8+g)*BSTR + ks*8 + 2*q4);
                    mma16(s[nb], qA[ks].x, qB[ks].x, qA[ks].y, qB[ks].y, bb.x, bb.y);
                }
            }
            // pass 1: Ql(smem) * Kh
#pragma unroll
            for (int ks = 0; ks < 4; ks++) {
                uint2 aA = *(const uint2*)(Ql +  r0    *BSTR + ks*8 + 2*q4);
                uint2 aB = *(const uint2*)(Ql + (r0+8) *BSTR + ks*8 + 2*q4);
#pragma unroll
                for (int nb = 0; nb < 4; nb++) {
                    uint2 bb = *(const uint2*)(Kh + ((4*h+nb)*8+g)*BSTR + ks*8 + 2*q4);
                    mma16(s[nb], aA.x, aB.x, aA.y, aB.y, bb.x, bb.y);
                }
            }
#pragma unroll
            for (int nb = 0; nb < 4; nb++)
#pragma unroll
                for (int j = 0; j < 4; j++) s[nb][j] *= 4.8828125e-4f;   // /2048
            // pass 2: exact hh
#pragma unroll
            for (int ks = 0; ks < 4; ks++) {
#pragma unroll
                for (int nb = 0; nb < 4; nb++) {
                    uint2 bb = *(const uint2*)(Kh + ((4*h+nb)*8+g)*BSTR + ks*8 + 2*q4);
                    mma16(s[nb], qA[ks].x, qB[ks].x, qA[ks].y, qB[ks].y, bb.x, bb.y);
                }
            }

            // ---- online softmax for this half ----
            float mx0 = -3.0e38f, mx1 = -3.0e38f;
#pragma unroll
            for (int nb = 0; nb < 4; nb++) {
                mx0 = fmaxf(mx0, fmaxf(s[nb][0], s[nb][1]));
                mx1 = fmaxf(mx1, fmaxf(s[nb][2], s[nb][3]));
            }
            mx0 = fmaxf(mx0, __shfl_xor_sync(0xffffffffu, mx0, 1));
            mx0 = fmaxf(mx0, __shfl_xor_sync(0xffffffffu, mx0, 2));
            mx1 = fmaxf(mx1, __shfl_xor_sync(0xffffffffu, mx1, 1));
            mx1 = fmaxf(mx1, __shfl_xor_sync(0xffffffffu, mx1, 2));
            float mn0 = fmaxf(m0, mx0), mn1 = fmaxf(m1, mx1);
            bool chg = (mn0 != m0) || (mn1 != m1);
            if (__any_sync(0xffffffffu, chg)) {
                float c0f = __expf(m0 - mn0), c1f = __expf(m1 - mn1);
                d_l[0] *= c0f; d_l[1] *= c0f; d_l[2] *= c1f; d_l[3] *= c1f;
#pragma unroll
                for (int nb = 0; nb < 8; nb++) {
                    o[nb][0] *= c0f; o[nb][1] *= c0f;
                    o[nb][2] *= c1f; o[nb][3] *= c1f;
                }
            }
            m0 = mn0; m1 = mn1;

            // ---- exp (f16x2 ex2) + l via ones-MMA + PV ----
            float ml0 = mn0 * L2E, ml1 = mn1 * L2E;
#pragma unroll
            for (int k = 0; k < 2; k++) {
                float t0 = fmaf(s[2*k  ][0], L2E, -ml0);
                float t1 = fmaf(s[2*k  ][1], L2E, -ml0);
                float t2 = fmaf(s[2*k  ][2], L2E, -ml1);
                float t3 = fmaf(s[2*k  ][3], L2E, -ml1);
                uint32_t a0 = packh(t0, t1);
                uint32_t a1 = packh(t2, t3);
                t0 = fmaf(s[2*k+1][0], L2E, -ml0);
                t1 = fmaf(s[2*k+1][1], L2E, -ml0);
                t2 = fmaf(s[2*k+1][2], L2E, -ml1);
                t3 = fmaf(s[2*k+1][3], L2E, -ml1);
                uint32_t a2 = packh(t0, t1);
                uint32_t a3 = packh(t2, t3);
                HEX2(a0); HEX2(a1); HEX2(a2); HEX2(a3);
                mma16(d_l, a0, a1, a2, a3, bones, bones);
#pragma unroll
                for (int nb = 0; nb < 8; nb++) {
                    uint2 bb = *(const uint2*)(Vt + (nb*8+g)*BSTR + (2*h+k)*8 + 2*q4);
                    mma16(o[nb], a0, a1, a2, a3, bb.x, bb.y);
                }
            }
        }
        buf++; if (buf == 3) buf = 0;
    }

    // ---- epilogue ----
    float lr0 = __shfl_sync(0xffffffffu, d_l[0], lane & 28);
    float lr1 = __shfl_sync(0xffffffffu, d_l[2], lane & 28);
    float i0 = 1.f / lr0, i1 = 1.f / lr1;
    float* ob = outp + (size_t)b * 64 * N;
    const int q0 = qt * 128;
#pragma unroll
    for (int nb = 0; nb < 8; nb++) {
        int cix = nb*8 + 2*q4;
        ob[(size_t) cix   *N + q0 + r0    ] = o[nb][0]*i0;
        ob[(size_t)(cix+1)*N + q0 + r0    ] = o[nb][1]*i0;
        ob[(size_t) cix   *N + q0 + r0 + 8] = o[nb][2]*i1;
        ob[(size_t)(cix+1)*N + q0 + r0 + 8] = o[nb][3]*i1;
    }
}

// ---------------- Stage 3: bilinear upsample + residual (float4 vectorized) ----------------
__device__ __forceinline__ float bilin(const float* __restrict__ p, int hp,
                                       int y, int x, float inv_s) {
    float sy = (y + 0.5f)*inv_s - 0.5f;
    float sx = (x + 0.5f)*inv_s - 0.5f;
    float fy = floorf(sy), fx = floorf(sx);
    float wy = sy - fy, wx = sx - fx;
    int y0 = max((int)fy, 0), y1 = min((int)fy + 1, hp-1);
    int x0 = max((int)fx, 0), x1 = min((int)fx + 1, hp-1);
    float a = p[y0*hp + x0], b2 = p[y0*hp + x1];
    float c2 = p[y1*hp + x0], d2 = p[y1*hp + x1];
    return (a*(1.f-wx) + b2*wx)*(1.f-wy) + (c2*(1.f-wx) + d2*wx)*wy;
}

__global__ void __launch_bounds__(256) final_kernel(const float* __restrict__ x,
                                                    float* __restrict__ out) {
    int i4 = blockIdx.x*256 + threadIdx.x;      // one float4 per thread
    if (i4 >= BB*CC*HH*WW/4) return;
    int base = i4 * 4;
    int xx = base & 63, yy = (base >> 6) & 63, bc = base >> 12;
    float4 xv = *(const float4*)(x + base);
    float4 ov = *(const float4*)(g_o1 + base);
    const float* p2 = g_o2 + bc*1024;
    const float* p4 = g_o4 + bc*256;
    float4 r;
    r.x = xv.x + ov.x + bilin(p2, 32, yy, xx+0, 0.5f) + bilin(p4, 16, yy, xx+0, 0.25f);
    r.y = xv.y + ov.y + bilin(p2, 32, yy, xx+1, 0.5f) + bilin(p4, 16, yy, xx+1, 0.25f);
    r.z = xv.z + ov.z + bilin(p2, 32, yy, xx+2, 0.5f) + bilin(p4, 16, yy, xx+2, 0.25f);
    r.w = xv.w + ov.w + bilin(p2, 32, yy, xx+3, 0.5f) + bilin(p4, 16, yy, xx+3, 0.25f);
    *(float4*)(out + base) = r;
}

// ---------------- launch ----------------
extern "C" void kernel_launch(void* const* d_in, const int* in_sizes, int n_in,
                              void* d_out, int out_size) {
    const float* x = (const float*)d_in[0];
    const float* w = (const float*)d_in[1];
    float* out = (float*)d_out;

    cudaFuncSetAttribute(attn_fused, cudaFuncAttributeMaxDynamicSharedMemorySize, ATTN_SMEM);
    cudaFuncSetAttribute(convmma_kernel, cudaFuncAttributeMaxDynamicSharedMemorySize, CONV_SMEM);

    wpack_kernel<<<72, 256>>>(w);
    convmma_kernel<<<dim3(64, 8), 128, CONV_SMEM>>>(x);
    poolpack_kernel<<<dim3(84, 8), 256>>>();
    attn_fused<<<dim3(42, 8), 256, ATTN_SMEM>>>();
    final_kernel<<<(BB*CC*HH*WW/4 + 255)/256, 256>>>(x, out);
}